// round 1
// baseline (speedup 1.0000x reference)
#include <cuda_runtime.h>

#define NN   2048
#define ORD  3
#define PTS  16
#define DIM1 64
#define DIM2 32
#define PL1  32
#define PL2  8
#define LBL  10

// Scratch (no allocations allowed in kernel_launch)
__device__ float g_ms[NN * ORD * PTS];   // [n, order*pts]
__device__ float g_h2[NN * DIM2];        // [n, 32]
__device__ float g_s [NN * PL2];         // [n, 8] pre-softmax attention logits
__device__ float g_g [PL2 * DIM2];       // [8, 32] pooled graph embedding

// ---------------------------------------------------------------------------
// Kernel 1 (dominant): feats[o,p,i] = mean_j cos(wm[o,p] * adj[o,i,j])
// written directly in transposed/concatenated layout ms[i, o*16+p].
// One block per (i, o); 256 threads; 16 accumulators per thread; MUFU-bound.
// ---------------------------------------------------------------------------
__global__ __launch_bounds__(256) void k_feats(const float* __restrict__ adj,
                                               const float* __restrict__ wm) {
    const int i = blockIdx.x, o = blockIdx.y, tid = threadIdx.x;

    __shared__ float ws[PTS];
    if (tid < PTS) ws[tid] = wm[o * PTS + tid];
    __syncthreads();

    float w[PTS], acc[PTS];
#pragma unroll
    for (int p = 0; p < PTS; p++) { w[p] = ws[p]; acc[p] = 0.f; }

    const float4* row = reinterpret_cast<const float4*>(
        adj + ((size_t)o * NN + i) * NN);

#pragma unroll
    for (int jj = 0; jj < NN / (256 * 4); jj++) {
        float4 a = row[tid + jj * 256];
#pragma unroll
        for (int p = 0; p < PTS; p++) {
            acc[p] += __cosf(w[p] * a.x) + __cosf(w[p] * a.y)
                    + __cosf(w[p] * a.z) + __cosf(w[p] * a.w);
        }
    }

    // warp reduce all 16 sums
#pragma unroll
    for (int ofs = 16; ofs; ofs >>= 1)
#pragma unroll
        for (int p = 0; p < PTS; p++)
            acc[p] += __shfl_xor_sync(0xffffffffu, acc[p], ofs);

    __shared__ float red[8][PTS];
    const int warp = tid >> 5, lane = tid & 31;
    if (lane == 0) {
#pragma unroll
        for (int p = 0; p < PTS; p++) red[warp][p] = acc[p];
    }
    __syncthreads();

    if (tid < PTS) {
        float s = 0.f;
#pragma unroll
        for (int wz = 0; wz < 8; wz++) s += red[wz][tid];
        g_ms[(size_t)i * (ORD * PTS) + o * PTS + tid] = s * (1.0f / NN);
    }
}

// ---------------------------------------------------------------------------
// Kernel 2: per-row MLP chain
//   h1 = relu(ms @ w1 + b1); h2 = relu(h1 @ w2 + b2);
//   ab = tanh(h2 @ p1 + pb1); s  = ab @ p2 + pb2
// Block of 128 threads handles 16 rows; 8 threads per row (output split).
// Weights staged in shared memory (broadcast reads).
// ---------------------------------------------------------------------------
__global__ __launch_bounds__(128) void k_mlp(
    const float* __restrict__ w1, const float* __restrict__ b1,
    const float* __restrict__ w2, const float* __restrict__ b2,
    const float* __restrict__ p1, const float* __restrict__ pb1,
    const float* __restrict__ p2, const float* __restrict__ pb2) {

    __shared__ float s_w1[48 * 64];
    __shared__ float s_w2[64 * 32];
    __shared__ float s_p1[32 * 32];
    __shared__ float s_p2[32 * 8];
    __shared__ float s_b1[64], s_b2[32], s_pb1[32], s_pb2[8];
    __shared__ float s_ms[16][49];
    __shared__ float s_h1[16][65];
    __shared__ float s_h2[16][33];
    __shared__ float s_ab[16][33];

    const int tid = threadIdx.x;
    const int row0 = blockIdx.x * 16;

    for (int k = tid; k < 48 * 64; k += 128) s_w1[k] = w1[k];
    for (int k = tid; k < 64 * 32; k += 128) s_w2[k] = w2[k];
    for (int k = tid; k < 32 * 32; k += 128) s_p1[k] = p1[k];
    for (int k = tid; k < 32 * 8;  k += 128) s_p2[k] = p2[k];
    if (tid < 64) s_b1[tid] = b1[tid];
    if (tid < 32) { s_b2[tid] = b2[tid]; s_pb1[tid] = pb1[tid]; }
    if (tid < 8)  s_pb2[tid] = pb2[tid];
    for (int k = tid; k < 16 * 48; k += 128) {
        int r = k / 48, kk = k % 48;
        s_ms[r][kk] = g_ms[(size_t)(row0 + r) * 48 + kk];
    }
    __syncthreads();

    const int r = tid >> 3, q = tid & 7;
    const int grow = row0 + r;

    // h1: each thread computes 8 of 64 outputs
#pragma unroll
    for (int dd = 0; dd < 8; dd++) {
        const int d = q * 8 + dd;
        float acc = s_b1[d];
#pragma unroll
        for (int k = 0; k < 48; k++) acc += s_ms[r][k] * s_w1[k * 64 + d];
        s_h1[r][d] = fmaxf(acc, 0.f);
    }
    __syncthreads();

    // h2: each thread computes 4 of 32 outputs
#pragma unroll
    for (int dd = 0; dd < 4; dd++) {
        const int d = q * 4 + dd;
        float acc = s_b2[d];
#pragma unroll
        for (int k = 0; k < 64; k++) acc += s_h1[r][k] * s_w2[k * 32 + d];
        acc = fmaxf(acc, 0.f);
        s_h2[r][d] = acc;
        g_h2[(size_t)grow * 32 + d] = acc;
    }
    __syncthreads();

    // abstract = tanh(h2 @ p1 + pb1)
#pragma unroll
    for (int dd = 0; dd < 4; dd++) {
        const int d = q * 4 + dd;
        float acc = s_pb1[d];
#pragma unroll
        for (int k = 0; k < 32; k++) acc += s_h2[r][k] * s_p1[k * 32 + d];
        s_ab[r][d] = tanhf(acc);
    }
    __syncthreads();

    // attention logits: thread q computes column c = q
    {
        const int c = q;
        float acc = s_pb2[c];
#pragma unroll
        for (int k = 0; k < 32; k++) acc += s_ab[r][k] * s_p2[k * 8 + c];
        g_s[(size_t)grow * 8 + c] = acc;
    }
}

// ---------------------------------------------------------------------------
// Kernel 3: softmax over nodes (axis 0) per pool column + weighted pooling
//   g[c, d] = sum_j softmax_j(s[:,c]) * h2[j, d]
// One block per column c (8 blocks, 256 threads).
// ---------------------------------------------------------------------------
__global__ __launch_bounds__(256) void k_pool() {
    const int c = blockIdx.x, tid = threadIdx.x;
    const int lane = tid & 31, warp = tid >> 5;

    float sv[8];
#pragma unroll
    for (int jj = 0; jj < 8; jj++) sv[jj] = g_s[(size_t)(tid + jj * 256) * 8 + c];

    float mx = sv[0];
#pragma unroll
    for (int jj = 1; jj < 8; jj++) mx = fmaxf(mx, sv[jj]);
#pragma unroll
    for (int ofs = 16; ofs; ofs >>= 1)
        mx = fmaxf(mx, __shfl_xor_sync(0xffffffffu, mx, ofs));

    __shared__ float sred[8];
    if (lane == 0) sred[warp] = mx;
    __syncthreads();
    float bm = sred[0];
#pragma unroll
    for (int wz = 1; wz < 8; wz++) bm = fmaxf(bm, sred[wz]);
    __syncthreads();  // before reusing sred

    float e[8], sum = 0.f;
#pragma unroll
    for (int jj = 0; jj < 8; jj++) { e[jj] = __expf(sv[jj] - bm); sum += e[jj]; }
#pragma unroll
    for (int ofs = 16; ofs; ofs >>= 1)
        sum += __shfl_xor_sync(0xffffffffu, sum, ofs);
    if (lane == 0) sred[warp] = sum;
    __syncthreads();
    float S = 0.f;
#pragma unroll
    for (int wz = 0; wz < 8; wz++) S += sred[wz];

    float acc[32];
#pragma unroll
    for (int d = 0; d < 32; d++) acc[d] = 0.f;
#pragma unroll
    for (int jj = 0; jj < 8; jj++) {
        const int j = tid + jj * 256;
        const float4* hr = reinterpret_cast<const float4*>(g_h2 + (size_t)j * 32);
#pragma unroll
        for (int qq = 0; qq < 8; qq++) {
            float4 v = hr[qq];
            acc[qq * 4 + 0] += e[jj] * v.x;
            acc[qq * 4 + 1] += e[jj] * v.y;
            acc[qq * 4 + 2] += e[jj] * v.z;
            acc[qq * 4 + 3] += e[jj] * v.w;
        }
    }
#pragma unroll
    for (int ofs = 16; ofs; ofs >>= 1)
#pragma unroll
        for (int d = 0; d < 32; d++)
            acc[d] += __shfl_xor_sync(0xffffffffu, acc[d], ofs);

    __shared__ float wred[8][32];
    if (lane == 0) {
#pragma unroll
        for (int d = 0; d < 32; d++) wred[warp][d] = acc[d];
    }
    __syncthreads();
    if (tid < 32) {
        float s2 = 0.f;
#pragma unroll
        for (int wz = 0; wz < 8; wz++) s2 += wred[wz][tid];
        g_g[c * 32 + tid] = s2 / S;
    }
}

// ---------------------------------------------------------------------------
// Kernel 4: logits = g @ cw + cb ; out = log_softmax(logits)
// One warp; lanes 0..9 each own one label.
// ---------------------------------------------------------------------------
__global__ __launch_bounds__(32) void k_head(const float* __restrict__ cw,
                                             const float* __restrict__ cb,
                                             float* __restrict__ out) {
    const int l = threadIdx.x;
    float logit = -1e30f;
    if (l < LBL) {
        float acc = cb[l];
        for (int k = 0; k < PL2 * DIM2; k++) acc += g_g[k] * cw[k * LBL + l];
        logit = acc;
    }
    float mx = logit;
#pragma unroll
    for (int ofs = 16; ofs; ofs >>= 1)
        mx = fmaxf(mx, __shfl_xor_sync(0xffffffffu, mx, ofs));
    float ex = (l < LBL) ? expf(logit - mx) : 0.f;
    float s = ex;
#pragma unroll
    for (int ofs = 16; ofs; ofs >>= 1)
        s += __shfl_xor_sync(0xffffffffu, s, ofs);
    if (l < LBL) out[l] = logit - mx - logf(s);
}

// ---------------------------------------------------------------------------
extern "C" void kernel_launch(void* const* d_in, const int* in_sizes, int n_in,
                              void* d_out, int out_size) {
    const float* adj = (const float*)d_in[0];
    const float* wm  = (const float*)d_in[1];
    const float* w1  = (const float*)d_in[2];
    const float* b1  = (const float*)d_in[3];
    const float* w2  = (const float*)d_in[4];
    const float* b2  = (const float*)d_in[5];
    const float* p1  = (const float*)d_in[6];
    const float* pb1 = (const float*)d_in[7];
    const float* p2  = (const float*)d_in[8];
    const float* pb2 = (const float*)d_in[9];
    const float* cw  = (const float*)d_in[10];
    const float* cb  = (const float*)d_in[11];
    float* out = (float*)d_out;

    dim3 g1(NN, ORD);
    k_feats<<<g1, 256>>>(adj, wm);
    k_mlp<<<NN / 16, 128>>>(w1, b1, w2, b2, p1, pb1, p2, pb2);
    k_pool<<<PL2, 256>>>();
    k_head<<<1, 32>>>(cw, cb, out);
}

// round 2
// speedup vs baseline: 1.1163x; 1.1163x over previous
#include <cuda_runtime.h>

#define NN   2048
#define ORD  3
#define PTS  16
#define DIM1 64
#define DIM2 32
#define PL1  32
#define PL2  8
#define LBL  10

// Scratch (no allocations allowed)
__device__ float    g_h2[NN * DIM2];   // [n, 32]
__device__ float    g_s [NN * PL2];    // [n, 8] attention logits
__device__ float    g_g [PL2 * DIM2];  // [8, 32] pooled embedding
__device__ unsigned g_cnt;             // pool completion counter (zero-init, self-resetting)

__device__ __forceinline__ float fast_tanh(float x) {
    float r;
    asm("tanh.approx.f32 %0, %1;" : "=f"(r) : "f"(x));
    return r;
}

// ---------------------------------------------------------------------------
// Kernel A (dominant, fused): for row i,
//   ms[o*16+p] = mean_j cos(wm[o,p] * adj[o,i,j])   (MUFU-bound, 3*2048*16 cos)
// then the per-row MLP chain:
//   h1 = relu(ms@w1+b1); h2 = relu(h1@w2+b2); ab = tanh(h2@p1+pb1); s = ab@p2+pb2
// One block per row; 256 threads.
// ---------------------------------------------------------------------------
__global__ __launch_bounds__(256) void k_row(
    const float* __restrict__ adj, const float* __restrict__ wm,
    const float* __restrict__ w1, const float* __restrict__ b1,
    const float* __restrict__ w2, const float* __restrict__ b2,
    const float* __restrict__ p1, const float* __restrict__ pb1,
    const float* __restrict__ p2, const float* __restrict__ pb2) {

    const int i = blockIdx.x, tid = threadIdx.x;
    const int warp = tid >> 5, lane = tid & 31;

    __shared__ float red[8][PTS];
    __shared__ float s_ms[ORD * PTS];
    __shared__ float s_h1[DIM1];
    __shared__ float s_h2[DIM2];
    __shared__ float s_ab[PL1];

    for (int o = 0; o < ORD; o++) {
        float w[PTS], acc[PTS];
#pragma unroll
        for (int p = 0; p < PTS; p++) {
            w[p] = __ldg(wm + o * PTS + p);
            acc[p] = 0.f;
        }

        const float4* row = reinterpret_cast<const float4*>(
            adj + ((size_t)o * NN + i) * NN);

#pragma unroll
        for (int jj = 0; jj < NN / (256 * 4); jj++) {
            float4 a = row[tid + jj * 256];
#pragma unroll
            for (int p = 0; p < PTS; p++) {
                acc[p] += (__cosf(w[p] * a.x) + __cosf(w[p] * a.y))
                        + (__cosf(w[p] * a.z) + __cosf(w[p] * a.w));
            }
        }

#pragma unroll
        for (int ofs = 16; ofs; ofs >>= 1)
#pragma unroll
            for (int p = 0; p < PTS; p++)
                acc[p] += __shfl_xor_sync(0xffffffffu, acc[p], ofs);

        __syncthreads();   // red[] safe to overwrite (prev o consumed)
        if (lane == 0) {
#pragma unroll
            for (int p = 0; p < PTS; p++) red[warp][p] = acc[p];
        }
        __syncthreads();

        if (tid < PTS) {
            float s = 0.f;
#pragma unroll
            for (int wz = 0; wz < 8; wz++) s += red[wz][tid];
            s_ms[o * PTS + tid] = s * (1.0f / NN);
        }
    }
    __syncthreads();

    // ---- MLP chain for this row (weights served from L2) ----
    if (tid < DIM1) {
        float a = __ldg(b1 + tid);
#pragma unroll
        for (int k = 0; k < ORD * PTS; k++) a = fmaf(s_ms[k], __ldg(w1 + k * DIM1 + tid), a);
        s_h1[tid] = fmaxf(a, 0.f);
    }
    __syncthreads();

    if (tid < DIM2) {
        float a = __ldg(b2 + tid);
#pragma unroll
        for (int k = 0; k < DIM1; k++) a = fmaf(s_h1[k], __ldg(w2 + k * DIM2 + tid), a);
        a = fmaxf(a, 0.f);
        s_h2[tid] = a;
        g_h2[(size_t)i * DIM2 + tid] = a;
    }
    __syncthreads();

    if (tid < PL1) {
        float a = __ldg(pb1 + tid);
#pragma unroll
        for (int k = 0; k < DIM2; k++) a = fmaf(s_h2[k], __ldg(p1 + k * PL1 + tid), a);
        s_ab[tid] = fast_tanh(a);
    }
    __syncthreads();

    if (tid < PL2) {
        float a = __ldg(pb2 + tid);
#pragma unroll
        for (int k = 0; k < PL1; k++) a = fmaf(s_ab[k], __ldg(p2 + k * PL2 + tid), a);
        g_s[(size_t)i * PL2 + tid] = a;
    }
}

// ---------------------------------------------------------------------------
// Kernel B: per-column node softmax + weighted pooling; last block does head.
//   g[c,d] = sum_j softmax_j(s[:,c]) * h2[j,d]
//   out    = log_softmax(g_flat @ cw + cb)
// 8 blocks x 256 threads; block finishing last (atomic counter) runs the head.
// ---------------------------------------------------------------------------
__global__ __launch_bounds__(256) void k_pool(const float* __restrict__ cw,
                                              const float* __restrict__ cb,
                                              float* __restrict__ out) {
    const int c = blockIdx.x, tid = threadIdx.x;
    const int lane = tid & 31, warp = tid >> 5;

    float sv[8];
#pragma unroll
    for (int jj = 0; jj < 8; jj++) sv[jj] = g_s[(size_t)(tid + jj * 256) * PL2 + c];

    float mx = sv[0];
#pragma unroll
    for (int jj = 1; jj < 8; jj++) mx = fmaxf(mx, sv[jj]);
#pragma unroll
    for (int ofs = 16; ofs; ofs >>= 1)
        mx = fmaxf(mx, __shfl_xor_sync(0xffffffffu, mx, ofs));

    __shared__ float sred[8];
    if (lane == 0) sred[warp] = mx;
    __syncthreads();
    float bm = sred[0];
#pragma unroll
    for (int wz = 1; wz < 8; wz++) bm = fmaxf(bm, sred[wz]);
    __syncthreads();

    float e[8], sum = 0.f;
#pragma unroll
    for (int jj = 0; jj < 8; jj++) { e[jj] = __expf(sv[jj] - bm); sum += e[jj]; }
#pragma unroll
    for (int ofs = 16; ofs; ofs >>= 1)
        sum += __shfl_xor_sync(0xffffffffu, sum, ofs);
    if (lane == 0) sred[warp] = sum;
    __syncthreads();
    float S = 0.f;
#pragma unroll
    for (int wz = 0; wz < 8; wz++) S += sred[wz];

    float acc[DIM2];
#pragma unroll
    for (int d = 0; d < DIM2; d++) acc[d] = 0.f;
#pragma unroll
    for (int jj = 0; jj < 8; jj++) {
        const int j = tid + jj * 256;
        const float4* hr = reinterpret_cast<const float4*>(g_h2 + (size_t)j * DIM2);
#pragma unroll
        for (int qq = 0; qq < 8; qq++) {
            float4 v = hr[qq];
            acc[qq * 4 + 0] += e[jj] * v.x;
            acc[qq * 4 + 1] += e[jj] * v.y;
            acc[qq * 4 + 2] += e[jj] * v.z;
            acc[qq * 4 + 3] += e[jj] * v.w;
        }
    }
#pragma unroll
    for (int ofs = 16; ofs; ofs >>= 1)
#pragma unroll
        for (int d = 0; d < DIM2; d++)
            acc[d] += __shfl_xor_sync(0xffffffffu, acc[d], ofs);

    __shared__ float wred[8][DIM2];
    if (lane == 0) {
#pragma unroll
        for (int d = 0; d < DIM2; d++) wred[warp][d] = acc[d];
    }
    __syncthreads();
    if (tid < DIM2) {
        float s2 = 0.f;
#pragma unroll
        for (int wz = 0; wz < 8; wz++) s2 += wred[wz][tid];
        __stcg(&g_g[c * DIM2 + tid], s2 / S);   // L2-visible for the last block
    }

    // ---- last-block-done head ----
    __shared__ unsigned s_last;
    __threadfence();
    __syncthreads();
    if (tid == 0) s_last = (atomicAdd(&g_cnt, 1u) == PL2 - 1u) ? 1u : 0u;
    __syncthreads();
    if (!s_last) return;

    // This block sees all g_g via L2 (__ldcg); producers fenced before atomic.
    __shared__ float part[8][LBL];
    {
        float v = __ldcg(&g_g[tid]);           // tid in [0,256)
        float p[LBL];
#pragma unroll
        for (int l = 0; l < LBL; l++) p[l] = v * __ldg(cw + tid * LBL + l);
#pragma unroll
        for (int ofs = 16; ofs; ofs >>= 1)
#pragma unroll
            for (int l = 0; l < LBL; l++)
                p[l] += __shfl_xor_sync(0xffffffffu, p[l], ofs);
        if (lane == 0) {
#pragma unroll
            for (int l = 0; l < LBL; l++) part[warp][l] = p[l];
        }
    }
    __syncthreads();

    if (tid < 32) {
        float logit = -1e30f;
        if (tid < LBL) {
            float a = __ldg(cb + tid);
#pragma unroll
            for (int wz = 0; wz < 8; wz++) a += part[wz][tid];
            logit = a;
        }
        float m2 = logit;
#pragma unroll
        for (int ofs = 16; ofs; ofs >>= 1)
            m2 = fmaxf(m2, __shfl_xor_sync(0xffffffffu, m2, ofs));
        float ex = (tid < LBL) ? expf(logit - m2) : 0.f;
        float s2 = ex;
#pragma unroll
        for (int ofs = 16; ofs; ofs >>= 1)
            s2 += __shfl_xor_sync(0xffffffffu, s2, ofs);
        if (tid < LBL) out[tid] = logit - m2 - logf(s2);
        if (tid == 0) atomicExch(&g_cnt, 0u);   // reset for next graph replay
    }
}

// ---------------------------------------------------------------------------
extern "C" void kernel_launch(void* const* d_in, const int* in_sizes, int n_in,
                              void* d_out, int out_size) {
    const float* adj = (const float*)d_in[0];
    const float* wm  = (const float*)d_in[1];
    const float* w1  = (const float*)d_in[2];
    const float* b1  = (const float*)d_in[3];
    const float* w2  = (const float*)d_in[4];
    const float* b2  = (const float*)d_in[5];
    const float* p1  = (const float*)d_in[6];
    const float* pb1 = (const float*)d_in[7];
    const float* p2  = (const float*)d_in[8];
    const float* pb2 = (const float*)d_in[9];
    const float* cw  = (const float*)d_in[10];
    const float* cb  = (const float*)d_in[11];
    float* out = (float*)d_out;

    k_row <<<NN, 256>>>(adj, wm, w1, b1, w2, b2, p1, pb1, p2, pb2);
    k_pool<<<PL2, 256>>>(cw, cb, out);
}

// round 3
// speedup vs baseline: 1.3261x; 1.1880x over previous
#include <cuda_runtime.h>

#define NN   2048
#define ORD  3
#define PTS  16
#define DIM1 64
#define DIM2 32
#define PL1  32
#define PL2  8
#define LBL  10

// Scratch accumulators (zero at module load; self-reset each launch)
__device__ float    g_num[PL2 * DIM2];  // sum_j e_j[c] * h2_j[d]
__device__ float    g_den[PL2];         // sum_j e_j[c]
__device__ unsigned g_cnt;              // completion counter

__device__ __forceinline__ float fast_tanh(float x) {
    float r;
    asm("tanh.approx.f32 %0, %1;" : "=f"(r) : "f"(x));
    return r;
}

// ---------------------------------------------------------------------------
// Single fused kernel. One block per node row i (256 threads):
//  1) ms[o*16+p] = mean_j cos(wm[o,p]*adj[o,i,j])           (MUFU-bound core)
//  2) h1=relu(ms@w1+b1); h2=relu(h1@w2+b2); ab=tanh(h2@p1+pb1); s=ab@p2+pb2
//  3) e[c]=exp(s[c]) (no max shift; |s|<~3) -> atomicAdd into g_num/g_den
//  4) last block: g = num/den; out = log_softmax(g_flat@cw+cb); reset accums
// ---------------------------------------------------------------------------
__global__ __launch_bounds__(256) void k_fused(
    const float* __restrict__ adj, const float* __restrict__ wm,
    const float* __restrict__ w1, const float* __restrict__ b1,
    const float* __restrict__ w2, const float* __restrict__ b2,
    const float* __restrict__ p1, const float* __restrict__ pb1,
    const float* __restrict__ p2, const float* __restrict__ pb2,
    const float* __restrict__ cw, const float* __restrict__ cb,
    float* __restrict__ out) {

    const int i = blockIdx.x, tid = threadIdx.x;
    const int warp = tid >> 5, lane = tid & 31;

    __shared__ float red[8][PTS];
    __shared__ float s_ms[ORD * PTS];
    __shared__ float s_h1[DIM1];
    __shared__ float s_h2[DIM2];
    __shared__ float s_ab[PL1];
    __shared__ float s_s[PL2];

    // ---- phase 1: characteristic features (201M cos chip-wide) ----
    for (int o = 0; o < ORD; o++) {
        float w[PTS], acc[PTS];
#pragma unroll
        for (int p = 0; p < PTS; p++) {
            w[p] = __ldg(wm + o * PTS + p);
            acc[p] = 0.f;
        }

        const float4* row = reinterpret_cast<const float4*>(
            adj + ((size_t)o * NN + i) * NN);

#pragma unroll
        for (int jj = 0; jj < NN / (256 * 4); jj++) {
            float4 a = row[tid + jj * 256];
#pragma unroll
            for (int p = 0; p < PTS; p++) {
                acc[p] += (__cosf(w[p] * a.x) + __cosf(w[p] * a.y))
                        + (__cosf(w[p] * a.z) + __cosf(w[p] * a.w));
            }
        }

#pragma unroll
        for (int ofs = 16; ofs; ofs >>= 1)
#pragma unroll
            for (int p = 0; p < PTS; p++)
                acc[p] += __shfl_xor_sync(0xffffffffu, acc[p], ofs);

        __syncthreads();
        if (lane == 0) {
#pragma unroll
            for (int p = 0; p < PTS; p++) red[warp][p] = acc[p];
        }
        __syncthreads();

        if (tid < PTS) {
            float s = 0.f;
#pragma unroll
            for (int wz = 0; wz < 8; wz++) s += red[wz][tid];
            s_ms[o * PTS + tid] = s * (1.0f / NN);
        }
    }
    __syncthreads();

    // ---- phase 2: per-row MLP chain (weights from L2) ----
    if (tid < DIM1) {
        float a = __ldg(b1 + tid);
#pragma unroll
        for (int k = 0; k < ORD * PTS; k++) a = fmaf(s_ms[k], __ldg(w1 + k * DIM1 + tid), a);
        s_h1[tid] = fmaxf(a, 0.f);
    }
    __syncthreads();

    if (tid < DIM2) {
        float a = __ldg(b2 + tid);
#pragma unroll
        for (int k = 0; k < DIM1; k++) a = fmaf(s_h1[k], __ldg(w2 + k * DIM2 + tid), a);
        s_h2[tid] = fmaxf(a, 0.f);
    }
    __syncthreads();

    if (tid < PL1) {
        float a = __ldg(pb1 + tid);
#pragma unroll
        for (int k = 0; k < DIM2; k++) a = fmaf(s_h2[k], __ldg(p1 + k * PL1 + tid), a);
        s_ab[tid] = fast_tanh(a);
    }
    __syncthreads();

    if (tid < PL2) {
        float a = __ldg(pb2 + tid);
#pragma unroll
        for (int k = 0; k < PL1; k++) a = fmaf(s_ab[k], __ldg(p2 + k * PL2 + tid), a);
        s_s[tid] = a;
    }
    __syncthreads();

    // ---- phase 3: unnormalized-softmax pooling contribution via atomics ----
    {
        const int c = tid >> 5, d = tid & 31;          // (c,d) covers 8x32
        float e = __expf(s_s[c]);                      // |s|<~3: safe unshifted
        atomicAdd(&g_num[tid], e * s_h2[d]);
        if (d == 0) atomicAdd(&g_den[c], e);
    }

    // ---- phase 4: last block computes head ----
    __shared__ unsigned s_last;
    __threadfence();
    __syncthreads();
    if (tid == 0) s_last = (atomicAdd(&g_cnt, 1u) == NN - 1u) ? 1u : 0u;
    __syncthreads();
    if (!s_last) return;

    __shared__ float part[8][LBL];
    float v = __ldcg(&g_num[tid]) / __ldcg(&g_den[tid >> 5]);
    {
        float p[LBL];
#pragma unroll
        for (int l = 0; l < LBL; l++) p[l] = v * __ldg(cw + tid * LBL + l);
#pragma unroll
        for (int ofs = 16; ofs; ofs >>= 1)
#pragma unroll
            for (int l = 0; l < LBL; l++)
                p[l] += __shfl_xor_sync(0xffffffffu, p[l], ofs);
        if (lane == 0) {
#pragma unroll
            for (int l = 0; l < LBL; l++) part[warp][l] = p[l];
        }
    }
    __syncthreads();

    if (tid < 32) {
        float logit = -1e30f;
        if (tid < LBL) {
            float a = __ldg(cb + tid);
#pragma unroll
            for (int wz = 0; wz < 8; wz++) a += part[wz][tid];
            logit = a;
        }
        float m2 = logit;
#pragma unroll
        for (int ofs = 16; ofs; ofs >>= 1)
            m2 = fmaxf(m2, __shfl_xor_sync(0xffffffffu, m2, ofs));
        float ex = (tid < LBL) ? expf(logit - m2) : 0.f;
        float s2 = ex;
#pragma unroll
        for (int ofs = 16; ofs; ofs >>= 1)
            s2 += __shfl_xor_sync(0xffffffffu, s2, ofs);
        if (tid < LBL) out[tid] = logit - m2 - logf(s2);
    }
    __syncthreads();   // all reads of g_num/g_den done (v consumed above)

    // reset accumulators for the next graph replay
    __stcg(&g_num[tid], 0.f);
    if (tid < PL2) __stcg(&g_den[tid], 0.f);
    if (tid == 0) { __threadfence(); atomicExch(&g_cnt, 0u); }
}

// ---------------------------------------------------------------------------
extern "C" void kernel_launch(void* const* d_in, const int* in_sizes, int n_in,
                              void* d_out, int out_size) {
    const float* adj = (const float*)d_in[0];
    const float* wm  = (const float*)d_in[1];
    const float* w1  = (const float*)d_in[2];
    const float* b1  = (const float*)d_in[3];
    const float* w2  = (const float*)d_in[4];
    const float* b2  = (const float*)d_in[5];
    const float* p1  = (const float*)d_in[6];
    const float* pb1 = (const float*)d_in[7];
    const float* p2  = (const float*)d_in[8];
    const float* pb2 = (const float*)d_in[9];
    const float* cw  = (const float*)d_in[10];
    const float* cb  = (const float*)d_in[11];
    float* out = (float*)d_out;

    k_fused<<<NN, 256>>>(adj, wm, w1, b1, w2, b2, p1, pb1, p2, pb2, cw, cb, out);
}

// round 4
// speedup vs baseline: 1.3480x; 1.0165x over previous
#include <cuda_runtime.h>

#define NN   2048
#define ORD  3
#define PTS  16
#define DIM1 64
#define DIM2 32
#define PL1  32
#define PL2  8
#define LBL  10
#define NPOLY 2                 // points [PTS-NPOLY, PTS) computed via FMA-pipe poly

// Scratch accumulators (zero at module load; self-reset each launch)
__device__ float    g_num[PL2 * DIM2];  // sum_j e_j[c] * h2_j[d]
__device__ float    g_den[PL2];         // sum_j e_j[c]
__device__ unsigned g_cnt;              // completion counter

__device__ __forceinline__ float fast_tanh(float x) {
    float r;
    asm("tanh.approx.f32 %0, %1;" : "=f"(r) : "f"(x));
    return r;
}

// cos(2*pi*y): exact reduction + even Taylor through (2*pi*t)^14, max err ~4e-6
__device__ __forceinline__ float cos2pi(float y) {
    float t = y - rintf(y);          // t in [-0.5, 0.5]
    float u = t * t;
    float p = -1.7143907f;           // -(2pi)^14/14!
    p = fmaf(p, u,  7.9035539f);     //  (2pi)^12/12!
    p = fmaf(p, u, -26.4257337f);    // -(2pi)^10/10!
    p = fmaf(p, u,  60.2446418f);    //  (2pi)^8/8!
    p = fmaf(p, u, -85.4567987f);    // -(2pi)^6/6!
    p = fmaf(p, u,  64.9393940f);    //  (2pi)^4/4!
    p = fmaf(p, u, -19.7392088f);    // -(2pi)^2/2!
    p = fmaf(p, u,  1.0f);
    return p;
}

__device__ __forceinline__ int bitrev4(int x) {
    return ((x & 1) << 3) | ((x & 2) << 1) | ((x & 4) >> 1) | ((x & 8) >> 3);
}

// ---------------------------------------------------------------------------
// Single fused kernel; one block (256 thr) per node row i.
// ---------------------------------------------------------------------------
__global__ __launch_bounds__(256) void k_fused(
    const float* __restrict__ adj, const float* __restrict__ wm,
    const float* __restrict__ w1, const float* __restrict__ b1,
    const float* __restrict__ w2, const float* __restrict__ b2,
    const float* __restrict__ p1, const float* __restrict__ pb1,
    const float* __restrict__ p2, const float* __restrict__ pb2,
    const float* __restrict__ cw, const float* __restrict__ cb,
    float* __restrict__ out) {

    const int i = blockIdx.x, tid = threadIdx.x;
    const int warp = tid >> 5, lane = tid & 31;

    __shared__ float s_w [ORD * PTS];   // raw weights (MUFU path)
    __shared__ float s_ws[ORD * PTS];   // weights / (2*pi)  (poly path)
    __shared__ float red[ORD][8][PTS];  // per-order per-warp partials (p = bitrev4(slot))
    __shared__ float s_ms[ORD * PTS];
    __shared__ float s_h1[DIM1];
    __shared__ float s_h2[DIM2];
    __shared__ float s_ab[PL1];
    __shared__ float s_s[PL2];

    if (tid < ORD * PTS) {
        float w = wm[tid];
        s_w[tid]  = w;
        s_ws[tid] = w * 0.15915494309189535f;   // 1/(2*pi)
    }
    __syncthreads();

    // ---- phase 1: characteristic features, 6 prefetched chunks ----
    const float4* row0 = reinterpret_cast<const float4*>(adj + ((size_t)0 * NN + i) * NN);
    const float4* row1 = reinterpret_cast<const float4*>(adj + ((size_t)1 * NN + i) * NN);
    const float4* row2 = reinterpret_cast<const float4*>(adj + ((size_t)2 * NN + i) * NN);

    float4 buf = row0[tid];             // chunk 0
    float acc[PTS];
#pragma unroll
    for (int p = 0; p < PTS; p++) acc[p] = 0.f;

#pragma unroll
    for (int c = 0; c < 2 * ORD; c++) {
        const int o = c >> 1;
        float4 cur = buf;
        if (c < 2 * ORD - 1) {          // prefetch next chunk
            const int cn = c + 1;
            const float4* nrow = (cn >> 1) == 0 ? row0 : ((cn >> 1) == 1 ? row1 : row2);
            buf = nrow[tid + (cn & 1) * 256];
        }

        // weights for this order
        float w[PTS - NPOLY], ws[NPOLY];
#pragma unroll
        for (int p = 0; p < PTS - NPOLY; p++) w[p] = s_w[o * PTS + p];
#pragma unroll
        for (int p = 0; p < NPOLY; p++) ws[p] = s_ws[o * PTS + (PTS - NPOLY) + p];

        const float xs[4] = {cur.x, cur.y, cur.z, cur.w};
#pragma unroll
        for (int e = 0; e < 4; e++) {
            const float x = xs[e];
#pragma unroll
            for (int p = 0; p < PTS - NPOLY; p++)
                acc[p] += __cosf(w[p] * x);               // MUFU path
#pragma unroll
            for (int p = 0; p < NPOLY; p++)
                acc[PTS - NPOLY + p] += cos2pi(ws[p] * x); // FMA path
        }

        if (c & 1) {
            // split-butterfly: halve accumulator count each step
            float v[PTS];
#pragma unroll
            for (int p = 0; p < PTS; p++) { v[p] = acc[p]; acc[p] = 0.f; }
#pragma unroll
            for (int s = 0; s < 4; s++) {
                const int bit = 1 << s, half = 8 >> s;
                const bool hi = lane & bit;
#pragma unroll
                for (int q = 0; q < 8; q++) {
                    if (q < half) {
                        float send = hi ? v[q] : v[q + half];
                        float recv = __shfl_xor_sync(0xffffffffu, send, bit);
                        v[q] = (hi ? v[q + half] : v[q]) + recv;
                    }
                }
            }
            v[0] += __shfl_xor_sync(0xffffffffu, v[0], 16);
            if (lane < PTS) red[o][warp][lane] = v[0];   // p = bitrev4(lane)
        }
    }
    __syncthreads();

    if (tid < ORD * PTS) {
        const int o = tid >> 4, l = tid & 15;
        float s = 0.f;
#pragma unroll
        for (int wz = 0; wz < 8; wz++) s += red[o][wz][l];
        s_ms[o * PTS + bitrev4(l)] = s * (1.0f / NN);
    }
    __syncthreads();

    // ---- phase 2: per-row MLP chain ----
    if (tid < DIM1) {
        float a = __ldg(b1 + tid);
#pragma unroll
        for (int k = 0; k < ORD * PTS; k++) a = fmaf(s_ms[k], __ldg(w1 + k * DIM1 + tid), a);
        s_h1[tid] = fmaxf(a, 0.f);
    }
    __syncthreads();

    if (tid < DIM2) {
        float a = __ldg(b2 + tid);
#pragma unroll
        for (int k = 0; k < DIM1; k++) a = fmaf(s_h1[k], __ldg(w2 + k * DIM2 + tid), a);
        s_h2[tid] = fmaxf(a, 0.f);
    }
    __syncthreads();

    if (tid < PL1) {
        float a = __ldg(pb1 + tid);
#pragma unroll
        for (int k = 0; k < DIM2; k++) a = fmaf(s_h2[k], __ldg(p1 + k * PL1 + tid), a);
        s_ab[tid] = fast_tanh(a);
    }
    __syncthreads();

    if (tid < PL2) {
        float a = __ldg(pb2 + tid);
#pragma unroll
        for (int k = 0; k < PL1; k++) a = fmaf(s_ab[k], __ldg(p2 + k * PL2 + tid), a);
        s_s[tid] = a;
    }
    __syncthreads();

    // ---- phase 3: unnormalized softmax pooling via atomics ----
    {
        const int c = tid >> 5, d = tid & 31;
        float e = __expf(s_s[c]);                // |s| small: safe unshifted
        atomicAdd(&g_num[tid], e * s_h2[d]);
        if (d == 0) atomicAdd(&g_den[c], e);
    }

    // ---- phase 4: last block does the head ----
    __shared__ unsigned s_last;
    __threadfence();
    __syncthreads();
    if (tid == 0) s_last = (atomicAdd(&g_cnt, 1u) == NN - 1u) ? 1u : 0u;
    __syncthreads();
    if (!s_last) return;

    __shared__ float part[8][LBL];
    float v = __ldcg(&g_num[tid]) / __ldcg(&g_den[tid >> 5]);
    {
        float p[LBL];
#pragma unroll
        for (int l = 0; l < LBL; l++) p[l] = v * __ldg(cw + tid * LBL + l);
#pragma unroll
        for (int ofs = 16; ofs; ofs >>= 1)
#pragma unroll
            for (int l = 0; l < LBL; l++)
                p[l] += __shfl_xor_sync(0xffffffffu, p[l], ofs);
        if (lane == 0) {
#pragma unroll
            for (int l = 0; l < LBL; l++) part[warp][l] = p[l];
        }
    }
    __syncthreads();

    if (tid < 32) {
        float logit = -1e30f;
        if (tid < LBL) {
            float a = __ldg(cb + tid);
#pragma unroll
            for (int wz = 0; wz < 8; wz++) a += part[wz][tid];
            logit = a;
        }
        float m2 = logit;
#pragma unroll
        for (int ofs = 16; ofs; ofs >>= 1)
            m2 = fmaxf(m2, __shfl_xor_sync(0xffffffffu, m2, ofs));
        float ex = (tid < LBL) ? expf(logit - m2) : 0.f;
        float s2 = ex;
#pragma unroll
        for (int ofs = 16; ofs; ofs >>= 1)
            s2 += __shfl_xor_sync(0xffffffffu, s2, ofs);
        if (tid < LBL) out[tid] = logit - m2 - logf(s2);
    }
    __syncthreads();

    // reset accumulators for next graph replay
    __stcg(&g_num[tid], 0.f);
    if (tid < PL2) __stcg(&g_den[tid], 0.f);
    if (tid == 0) { __threadfence(); atomicExch(&g_cnt, 0u); }
}

// ---------------------------------------------------------------------------
extern "C" void kernel_launch(void* const* d_in, const int* in_sizes, int n_in,
                              void* d_out, int out_size) {
    const float* adj = (const float*)d_in[0];
    const float* wm  = (const float*)d_in[1];
    const float* w1  = (const float*)d_in[2];
    const float* b1  = (const float*)d_in[3];
    const float* w2  = (const float*)d_in[4];
    const float* b2  = (const float*)d_in[5];
    const float* p1  = (const float*)d_in[6];
    const float* pb1 = (const float*)d_in[7];
    const float* p2  = (const float*)d_in[8];
    const float* pb2 = (const float*)d_in[9];
    const float* cw  = (const float*)d_in[10];
    const float* cb  = (const float*)d_in[11];
    float* out = (float*)d_out;

    k_fused<<<NN, 256>>>(adj, wm, w1, b1, w2, b2, p1, pb1, p2, pb2, cw, cb, out);
}

// round 5
// speedup vs baseline: 1.3488x; 1.0006x over previous
#include <cuda_runtime.h>

#define NN   2048
#define ORD  3
#define PTS  16
#define DIM1 64
#define DIM2 32
#define PL1  32
#define PL2  8
#define LBL  10

// Scratch accumulators (zero at module load; self-reset each launch)
__device__ float    g_num[PL2 * DIM2];
__device__ float    g_den[PL2];
__device__ unsigned g_cnt;

__device__ __forceinline__ float fast_tanh(float x) {
    float r;
    asm("tanh.approx.f32 %0, %1;" : "=f"(r) : "f"(x));
    return r;
}

// cos(2*pi*y): exact reduction + even poly through (2*pi*t)^14, max err ~4e-6
__device__ __forceinline__ float cos2pi(float y) {
    float t = y - rintf(y);
    float u = t * t;
    float p = -1.7143907f;
    p = fmaf(p, u,  7.9035539f);
    p = fmaf(p, u, -26.4257337f);
    p = fmaf(p, u,  60.2446418f);
    p = fmaf(p, u, -85.4567987f);
    p = fmaf(p, u,  64.9393940f);
    p = fmaf(p, u, -19.7392088f);
    p = fmaf(p, u,  1.0f);
    return p;
}

__device__ __forceinline__ int bitrev3(int x) {
    return ((x & 1) << 2) | (x & 2) | ((x & 4) >> 2);
}

// ---------------------------------------------------------------------------
// One block (256 thr, >=6 blocks/SM) per node row i.
// Phase 1: row data held in 8 registers; two 8-point sweeps per order.
// ---------------------------------------------------------------------------
__global__ __launch_bounds__(256, 6) void k_fused(
    const float* __restrict__ adj, const float* __restrict__ wm,
    const float* __restrict__ w1, const float* __restrict__ b1,
    const float* __restrict__ w2, const float* __restrict__ b2,
    const float* __restrict__ p1, const float* __restrict__ pb1,
    const float* __restrict__ p2, const float* __restrict__ pb2,
    const float* __restrict__ cw, const float* __restrict__ cb,
    float* __restrict__ out) {

    const int i = blockIdx.x, tid = threadIdx.x;
    const int warp = tid >> 5, lane = tid & 31;

    __shared__ float s_w [ORD * PTS];     // raw weights (MUFU path)
    __shared__ float s_ws[ORD * PTS];     // weights/(2pi) (poly path)
    __shared__ float red[ORD][8][PTS];    // per-order per-warp partials
    __shared__ float s_ms[ORD * PTS];
    __shared__ float s_h1[DIM1];
    __shared__ float s_h2[DIM2];
    __shared__ float s_ab[PL1];
    __shared__ float s_s[PL2];

    if (tid < ORD * PTS) {
        float w = wm[tid];
        s_w[tid]  = w;
        s_ws[tid] = w * 0.15915494309189535f;
    }
    __syncthreads();

    // ---- phase 1 ----
    const float* base = adj + (size_t)i * NN;
#pragma unroll
    for (int o = 0; o < ORD; o++) {
        const float4* row = reinterpret_cast<const float4*>(base + (size_t)o * NN * NN);
        const float4 c0 = row[tid];
        const float4 c1 = row[tid + 256];
        const float xs[8] = {c0.x, c0.y, c0.z, c0.w, c1.x, c1.y, c1.z, c1.w};

#pragma unroll
        for (int s = 0; s < 2; s++) {
            float w[7], acc[8];
#pragma unroll
            for (int q = 0; q < 7; q++) { w[q] = s_w[o * PTS + s * 8 + q]; acc[q] = 0.f; }
            const float wsp = s_ws[o * PTS + s * 8 + 7];
            acc[7] = 0.f;

#pragma unroll
            for (int e = 0; e < 8; e++) {
                const float x = xs[e];
#pragma unroll
                for (int q = 0; q < 7; q++) acc[q] += __cosf(w[q] * x);
                acc[7] += cos2pi(wsp * x);
            }

            // split-butterfly: 8 accs -> 1 per lane (point = bitrev3(lane&7))
#pragma unroll
            for (int st = 0; st < 3; st++) {
                const int bit = 1 << st, half = 8 >> (st + 1);
                const bool hi = lane & bit;
#pragma unroll
                for (int q = 0; q < 4; q++) {
                    if (q < half) {
                        float send = hi ? acc[q] : acc[q + half];
                        float recv = __shfl_xor_sync(0xffffffffu, send, bit);
                        acc[q] = (hi ? acc[q + half] : acc[q]) + recv;
                    }
                }
            }
            float v = acc[0];
            v += __shfl_xor_sync(0xffffffffu, v, 8);
            v += __shfl_xor_sync(0xffffffffu, v, 16);
            if (lane < 8) red[o][warp][s * 8 + lane] = v;
        }
    }
    __syncthreads();

    if (tid < ORD * PTS) {
        const int o = tid >> 4, l = tid & 15;
        float s = 0.f;
#pragma unroll
        for (int wz = 0; wz < 8; wz++) s += red[o][wz][l];
        s_ms[o * PTS + (l & 8) + bitrev3(l & 7)] = s * (1.0f / NN);
    }
    __syncthreads();

    // ---- phase 2: per-row MLP chain ----
    if (tid < DIM1) {
        float a = __ldg(b1 + tid);
#pragma unroll
        for (int k = 0; k < ORD * PTS; k++) a = fmaf(s_ms[k], __ldg(w1 + k * DIM1 + tid), a);
        s_h1[tid] = fmaxf(a, 0.f);
    }
    __syncthreads();

    if (tid < DIM2) {
        float a = __ldg(b2 + tid);
#pragma unroll
        for (int k = 0; k < DIM1; k++) a = fmaf(s_h1[k], __ldg(w2 + k * DIM2 + tid), a);
        s_h2[tid] = fmaxf(a, 0.f);
    }
    __syncthreads();

    if (tid < PL1) {
        float a = __ldg(pb1 + tid);
#pragma unroll
        for (int k = 0; k < DIM2; k++) a = fmaf(s_h2[k], __ldg(p1 + k * PL1 + tid), a);
        s_ab[tid] = fast_tanh(a);
    }
    __syncthreads();

    if (tid < PL2) {
        float a = __ldg(pb2 + tid);
#pragma unroll
        for (int k = 0; k < PL1; k++) a = fmaf(s_ab[k], __ldg(p2 + k * PL2 + tid), a);
        s_s[tid] = a;
    }
    __syncthreads();

    // ---- phase 3: unnormalized softmax pooling via atomics ----
    {
        const int c = tid >> 5, d = tid & 31;
        float e = __expf(s_s[c]);               // |s| small: safe unshifted
        atomicAdd(&g_num[tid], e * s_h2[d]);
        if (d == 0) atomicAdd(&g_den[c], e);
    }

    // ---- phase 4: last block computes head ----
    __shared__ unsigned s_last;
    __threadfence();
    __syncthreads();
    if (tid == 0) s_last = (atomicAdd(&g_cnt, 1u) == NN - 1u) ? 1u : 0u;
    __syncthreads();
    if (!s_last) return;

    __shared__ float part[8][LBL];
    float v = __ldcg(&g_num[tid]) / __ldcg(&g_den[tid >> 5]);
    {
        float p[LBL];
#pragma unroll
        for (int l = 0; l < LBL; l++) p[l] = v * __ldg(cw + tid * LBL + l);
#pragma unroll
        for (int ofs = 16; ofs; ofs >>= 1)
#pragma unroll
            for (int l = 0; l < LBL; l++)
                p[l] += __shfl_xor_sync(0xffffffffu, p[l], ofs);
        if (lane == 0) {
#pragma unroll
            for (int l = 0; l < LBL; l++) part[warp][l] = p[l];
        }
    }
    __syncthreads();

    if (tid < 32) {
        float logit = -1e30f;
        if (tid < LBL) {
            float a = __ldg(cb + tid);
#pragma unroll
            for (int wz = 0; wz < 8; wz++) a += part[wz][tid];
            logit = a;
        }
        float m2 = logit;
#pragma unroll
        for (int ofs = 16; ofs; ofs >>= 1)
            m2 = fmaxf(m2, __shfl_xor_sync(0xffffffffu, m2, ofs));
        float ex = (tid < LBL) ? expf(logit - m2) : 0.f;
        float s2 = ex;
#pragma unroll
        for (int ofs = 16; ofs; ofs >>= 1)
            s2 += __shfl_xor_sync(0xffffffffu, s2, ofs);
        if (tid < LBL) out[tid] = logit - m2 - logf(s2);
    }
    __syncthreads();

    // reset for next graph replay
    __stcg(&g_num[tid], 0.f);
    if (tid < PL2) __stcg(&g_den[tid], 0.f);
    if (tid == 0) { __threadfence(); atomicExch(&g_cnt, 0u); }
}

// ---------------------------------------------------------------------------
extern "C" void kernel_launch(void* const* d_in, const int* in_sizes, int n_in,
                              void* d_out, int out_size) {
    const float* adj = (const float*)d_in[0];
    const float* wm  = (const float*)d_in[1];
    const float* w1  = (const float*)d_in[2];
    const float* b1  = (const float*)d_in[3];
    const float* w2  = (const float*)d_in[4];
    const float* b2  = (const float*)d_in[5];
    const float* p1  = (const float*)d_in[6];
    const float* pb1 = (const float*)d_in[7];
    const float* p2  = (const float*)d_in[8];
    const float* pb2 = (const float*)d_in[9];
    const float* cw  = (const float*)d_in[10];
    const float* cb  = (const float*)d_in[11];
    float* out = (float*)d_out;

    k_fused<<<NN, 256>>>(adj, wm, w1, b1, w2, b2, p1, pb1, p2, pb2, cw, cb, out);
}